// round 10
// baseline (speedup 1.0000x reference)
#include <cuda_runtime.h>
#include <cuda_bf16.h>

#define B 32768
#define C 1000
#define NV4 250            // float4 per row
#define NBLK 4096          // 8 rows/block, 1 row/warp, wave-based (blocks exit)

// INVARIANTS at kernel_launch entry (zero at module load, restored by finisher):
//   g_cnt == 0, g_done == 0.
__device__ int      g_cnt[C];
__device__ float    g_row[B];
__device__ unsigned g_done;

__global__ __launch_bounds__(256) void kl_all_kernel(
    const float* __restrict__ f1,
    const float* __restrict__ f2,
    const int*   __restrict__ label,
    float*       __restrict__ out)
{
    __shared__ int   s_last;
    __shared__ float swarp[8];
    const int tid  = threadIdx.x;
    const int lane = tid & 31;
    const int wid  = tid >> 5;

    // ---- hist prologue: first 32 blocks cover all 32768 labels.
    // g_cnt has no reader until the finisher, so this overlaps with streaming.
    if (blockIdx.x < 32) {
        int i = blockIdx.x * 256 + tid;          // int4 index, 8192 total
        int4 L = ((const int4*)label)[i];
        atomicAdd(&g_cnt[min(max(L.x, 0), C - 1)], 1);
        atomicAdd(&g_cnt[min(max(L.y, 0), C - 1)], 1);
        atomicAdd(&g_cnt[min(max(L.z, 0), C - 1)], 1);
        atomicAdd(&g_cnt[min(max(L.w, 0), C - 1)], 1);
    }

    // ---- main: one row per warp; 16 float4 front-batched (the max pass
    // consumes the whole row before pass 2, forcing ptxas to batch all loads
    // -> high MLP_p1. This, not numerics, is why the max pass stays.) ----
    const int row = blockIdx.x * 8 + wid;
    const float4* p1 = (const float4*)f1 + (size_t)row * NV4;
    const float4* p2 = (const float4*)f2 + (size_t)row * NV4;

    float4 a[8], b[8];
    const float4 NEG = make_float4(-1e30f, -1e30f, -1e30f, -1e30f);
    #pragma unroll
    for (int k = 0; k < 8; k++) {
        int j = lane + 32 * k;
        if (j < NV4) { a[k] = p1[j]; b[k] = p2[j]; }
        else         { a[k] = NEG;   b[k] = NEG;   }
    }

    // pass 1: row maxes
    float m1 = -1e30f, m2 = -1e30f;
    #pragma unroll
    for (int k = 0; k < 8; k++) {
        m1 = fmaxf(m1, fmaxf(fmaxf(a[k].x, a[k].y), fmaxf(a[k].z, a[k].w)));
        m2 = fmaxf(m2, fmaxf(fmaxf(b[k].x, b[k].y), fmaxf(b[k].z, b[k].w)));
    }
    #pragma unroll
    for (int o = 16; o; o >>= 1) {
        m1 = fmaxf(m1, __shfl_xor_sync(0xFFFFFFFFu, m1, o));
        m2 = fmaxf(m2, __shfl_xor_sync(0xFFFFFFFFu, m2, o));
    }

    // pass 2 (registers): s1, s2, wv
    float s1 = 0.f, s2 = 0.f, wv = 0.f;
    #pragma unroll
    for (int k = 0; k < 8; k++) {
        s1 += __expf(a[k].x - m1) + __expf(a[k].y - m1)
            + __expf(a[k].z - m1) + __expf(a[k].w - m1);
        float e;
        e = __expf(b[k].x - m2); s2 += e; wv = fmaf(e, b[k].x - a[k].x, wv);
        e = __expf(b[k].y - m2); s2 += e; wv = fmaf(e, b[k].y - a[k].y, wv);
        e = __expf(b[k].z - m2); s2 += e; wv = fmaf(e, b[k].z - a[k].z, wv);
        e = __expf(b[k].w - m2); s2 += e; wv = fmaf(e, b[k].w - a[k].w, wv);
    }
    #pragma unroll
    for (int o = 16; o; o >>= 1) {
        s1 += __shfl_xor_sync(0xFFFFFFFFu, s1, o);
        s2 += __shfl_xor_sync(0xFFFFFFFFu, s2, o);
        wv += __shfl_xor_sync(0xFFFFFFFFu, wv, o);
    }
    if (lane == 0)
        g_row[row] = wv / s2 + (m1 + __logf(s1)) - (m2 + __logf(s2));

    // ---- ticket: last block to finish becomes the finisher ----
    __syncthreads();
    if (tid == 0) {
        __threadfence();
        unsigned old = atomicAdd(&g_done, 1u);
        s_last = (old == (unsigned)(NBLK - 1)) ? 1 : 0;
    }
    __syncthreads();
    if (!s_last) return;

    // ---- finisher: deterministic fixed-order reduction of g_row ----
    float s = 0.f;
    for (int i = tid; i < B / 4; i += 256) {
        float4 v = __ldcg((const float4*)g_row + i);
        int4   L = ((const int4*)label)[i];
        s += __fdividef(v.x, (float)max(__ldcg(g_cnt + min(max(L.x, 0), C - 1)), 1));
        s += __fdividef(v.y, (float)max(__ldcg(g_cnt + min(max(L.y, 0), C - 1)), 1));
        s += __fdividef(v.z, (float)max(__ldcg(g_cnt + min(max(L.z, 0), C - 1)), 1));
        s += __fdividef(v.w, (float)max(__ldcg(g_cnt + min(max(L.w, 0), C - 1)), 1));
    }
    #pragma unroll
    for (int o = 16; o; o >>= 1) s += __shfl_xor_sync(0xFFFFFFFFu, s, o);
    if (lane == 0) swarp[wid] = s;
    __syncthreads();
    if (tid == 0) {
        float r = 0.f;
        #pragma unroll
        for (int i = 0; i < 8; i++) r += swarp[i];
        out[0] = r * (1.0f / (float)C);
    }
    // restore invariants for the next call / graph replay
    __syncthreads();
    for (int i = tid; i < C; i += 256) g_cnt[i] = 0;
    if (tid == 0) g_done = 0u;
}

extern "C" void kernel_launch(void* const* d_in, const int* in_sizes, int n_in,
                              void* d_out, int out_size)
{
    const float* f1    = (const float*)d_in[0];
    const float* f2    = (const float*)d_in[1];
    const int*   label = (const int*)d_in[2];
    float*       out   = (float*)d_out;

    kl_all_kernel<<<NBLK, 256>>>(f1, f2, label, out);
}

// round 11
// speedup vs baseline: 1.5295x; 1.5295x over previous
#include <cuda_runtime.h>
#include <cuda_bf16.h>

#define B 32768
#define C 1000
#define NV4 250            // float4 per row
#define NBLK 4096          // 8 rows/block, 1 row/warp, wave-based
#define NFIN 32            // finisher blocks

// INVARIANTS at kernel_launch entry (zero at module load, restored by kl_final):
//   g_cnt == 0, g_done == 0.
__device__ int      g_cnt[C];
__device__ float    g_row[B];
__device__ float    g_part[NFIN];
__device__ unsigned g_done;

// ---- engine: R5 row_kl verbatim + hist prologue; writes RAW kl (no cnt) ----
__global__ __launch_bounds__(256) void kl_main_kernel(
    const float* __restrict__ f1,
    const float* __restrict__ f2,
    const int*   __restrict__ label)
{
    const int tid  = threadIdx.x;
    const int lane = tid & 31;
    const int wid  = tid >> 5;

    // hist prologue: blocks 0..31 cover all 32768 labels (int4 loads).
    // g_cnt has no reader until kl_final, so this overlaps with streaming.
    if (blockIdx.x < 32) {
        int i = blockIdx.x * 256 + tid;
        int4 L = ((const int4*)label)[i];
        atomicAdd(&g_cnt[min(max(L.x, 0), C - 1)], 1);
        atomicAdd(&g_cnt[min(max(L.y, 0), C - 1)], 1);
        atomicAdd(&g_cnt[min(max(L.z, 0), C - 1)], 1);
        atomicAdd(&g_cnt[min(max(L.w, 0), C - 1)], 1);
    }

    const int row = blockIdx.x * 8 + wid;
    const float4* p1 = (const float4*)f1 + (size_t)row * NV4;
    const float4* p2 = (const float4*)f2 + (size_t)row * NV4;

    float4 a[8], b[8];
    const float4 NEG = make_float4(-1e30f, -1e30f, -1e30f, -1e30f);
    #pragma unroll
    for (int k = 0; k < 8; k++) {
        int j = lane + 32 * k;
        if (j < NV4) { a[k] = p1[j]; b[k] = p2[j]; }
        else         { a[k] = NEG;   b[k] = NEG;   }
    }

    // pass 1: row maxes (consumes whole row -> ptxas front-batches all loads)
    float m1 = -1e30f, m2 = -1e30f;
    #pragma unroll
    for (int k = 0; k < 8; k++) {
        m1 = fmaxf(m1, fmaxf(fmaxf(a[k].x, a[k].y), fmaxf(a[k].z, a[k].w)));
        m2 = fmaxf(m2, fmaxf(fmaxf(b[k].x, b[k].y), fmaxf(b[k].z, b[k].w)));
    }
    #pragma unroll
    for (int o = 16; o; o >>= 1) {
        m1 = fmaxf(m1, __shfl_xor_sync(0xFFFFFFFFu, m1, o));
        m2 = fmaxf(m2, __shfl_xor_sync(0xFFFFFFFFu, m2, o));
    }

    // pass 2 (registers): s1, s2, wv
    float s1 = 0.f, s2 = 0.f, wv = 0.f;
    #pragma unroll
    for (int k = 0; k < 8; k++) {
        s1 += __expf(a[k].x - m1) + __expf(a[k].y - m1)
            + __expf(a[k].z - m1) + __expf(a[k].w - m1);
        float e;
        e = __expf(b[k].x - m2); s2 += e; wv = fmaf(e, b[k].x - a[k].x, wv);
        e = __expf(b[k].y - m2); s2 += e; wv = fmaf(e, b[k].y - a[k].y, wv);
        e = __expf(b[k].z - m2); s2 += e; wv = fmaf(e, b[k].z - a[k].z, wv);
        e = __expf(b[k].w - m2); s2 += e; wv = fmaf(e, b[k].w - a[k].w, wv);
    }
    #pragma unroll
    for (int o = 16; o; o >>= 1) {
        s1 += __shfl_xor_sync(0xFFFFFFFFu, s1, o);
        s2 += __shfl_xor_sync(0xFFFFFFFFu, s2, o);
        wv += __shfl_xor_sync(0xFFFFFFFFu, wv, o);
    }

    if (lane == 0)
        g_row[row] = wv / s2 + (m1 + __logf(s1)) - (m2 + __logf(s2));
}

// ---- finisher: 32 blocks, one int4 of rows per thread; last block (ticket)
// reduces the 32 partials in fixed order and restores invariants. ----
__global__ __launch_bounds__(256) void kl_final_kernel(
    const int* __restrict__ label,
    float*     __restrict__ out)
{
    __shared__ float swarp[8];
    __shared__ int   s_last;
    const int tid  = threadIdx.x;
    const int lane = tid & 31;
    const int wid  = tid >> 5;

    const int i = blockIdx.x * 256 + tid;        // int4 index, 8192 total
    float4 v = __ldcg((const float4*)g_row + i);
    int4   L = ((const int4*)label)[i];

    float s = 0.f;
    s += __fdividef(v.x, (float)max(g_cnt[min(max(L.x, 0), C - 1)], 1));
    s += __fdividef(v.y, (float)max(g_cnt[min(max(L.y, 0), C - 1)], 1));
    s += __fdividef(v.z, (float)max(g_cnt[min(max(L.z, 0), C - 1)], 1));
    s += __fdividef(v.w, (float)max(g_cnt[min(max(L.w, 0), C - 1)], 1));

    #pragma unroll
    for (int o = 16; o; o >>= 1) s += __shfl_xor_sync(0xFFFFFFFFu, s, o);
    if (lane == 0) swarp[wid] = s;
    __syncthreads();
    if (tid == 0) {
        float r = 0.f;
        #pragma unroll
        for (int k = 0; k < 8; k++) r += swarp[k];
        g_part[blockIdx.x] = r;
        __threadfence();
        unsigned old = atomicAdd(&g_done, 1u);
        s_last = (old == (unsigned)(NFIN - 1)) ? 1 : 0;
    }
    __syncthreads();
    if (!s_last) return;

    // last block: deterministic fixed-order sum of the 32 partials
    if (wid == 0) {
        float r = (lane < NFIN) ? __ldcg(g_part + lane) : 0.f;
        #pragma unroll
        for (int o = 16; o; o >>= 1) r += __shfl_xor_sync(0xFFFFFFFFu, r, o);
        if (lane == 0) out[0] = r * (1.0f / (float)C);
    }
    // restore invariants for next call / graph replay
    __syncthreads();
    for (int k = tid; k < C; k += 256) g_cnt[k] = 0;
    if (tid == 0) g_done = 0u;
}

extern "C" void kernel_launch(void* const* d_in, const int* in_sizes, int n_in,
                              void* d_out, int out_size)
{
    const float* f1    = (const float*)d_in[0];
    const float* f2    = (const float*)d_in[1];
    const int*   label = (const int*)d_in[2];
    float*       out   = (float*)d_out;

    kl_main_kernel<<<NBLK, 256>>>(f1, f2, label);
    kl_final_kernel<<<NFIN, 256>>>(label, out);
}

// round 12
// speedup vs baseline: 1.5306x; 1.0007x over previous
#include <cuda_runtime.h>
#include <cuda_bf16.h>

#define B 32768
#define C 1000
#define NV4 250            // float4 per row
#define NBLK 4096          // 8 rows/block, 1 row/warp, wave-based
#define NFIN 32            // finisher blocks

// INVARIANTS at kernel_launch entry (zero at module load, restored by kl_final):
//   g_cnt == 0, g_done == 0.
__device__ int      g_cnt[C];
__device__ float    g_row[B];
__device__ float    g_part[NFIN];
__device__ unsigned g_done;

// ---- engine: two-pass row KL + hist prologue; writes RAW kl (no cnt) ----
__global__ __launch_bounds__(256) void kl_main_kernel(
    const float* __restrict__ f1,
    const float* __restrict__ f2,
    const int*   __restrict__ label)
{
    const int tid  = threadIdx.x;
    const int lane = tid & 31;
    const int wid  = tid >> 5;

    // hist prologue: blocks 0..31 cover all 32768 labels (int4 loads).
    // g_cnt has no reader until kl_final, so this overlaps with streaming.
    if (blockIdx.x < 32) {
        int i = blockIdx.x * 256 + tid;
        int4 L = ((const int4*)label)[i];
        atomicAdd(&g_cnt[min(max(L.x, 0), C - 1)], 1);
        atomicAdd(&g_cnt[min(max(L.y, 0), C - 1)], 1);
        atomicAdd(&g_cnt[min(max(L.z, 0), C - 1)], 1);
        atomicAdd(&g_cnt[min(max(L.w, 0), C - 1)], 1);
    }

    const int row = blockIdx.x * 8 + wid;
    const float4* p1 = (const float4*)f1 + (size_t)row * NV4;
    const float4* p2 = (const float4*)f2 + (size_t)row * NV4;

    float4 a[8], b[8];
    const float4 NEG = make_float4(-1e30f, -1e30f, -1e30f, -1e30f);
    #pragma unroll
    for (int k = 0; k < 8; k++) {
        int j = lane + 32 * k;
        if (j < NV4) { a[k] = p1[j]; b[k] = p2[j]; }
        else         { a[k] = NEG;   b[k] = NEG;   }
    }

    // pass 1: row maxes (consumes whole row -> ptxas front-batches all loads)
    float m1 = -1e30f, m2 = -1e30f;
    #pragma unroll
    for (int k = 0; k < 8; k++) {
        m1 = fmaxf(m1, fmaxf(fmaxf(a[k].x, a[k].y), fmaxf(a[k].z, a[k].w)));
        m2 = fmaxf(m2, fmaxf(fmaxf(b[k].x, b[k].y), fmaxf(b[k].z, b[k].w)));
    }
    #pragma unroll
    for (int o = 16; o; o >>= 1) {
        m1 = fmaxf(m1, __shfl_xor_sync(0xFFFFFFFFu, m1, o));
        m2 = fmaxf(m2, __shfl_xor_sync(0xFFFFFFFFu, m2, o));
    }

    // pass 2 (registers): s1, s2, wv
    float s1 = 0.f, s2 = 0.f, wv = 0.f;
    #pragma unroll
    for (int k = 0; k < 8; k++) {
        s1 += __expf(a[k].x - m1) + __expf(a[k].y - m1)
            + __expf(a[k].z - m1) + __expf(a[k].w - m1);
        float e;
        e = __expf(b[k].x - m2); s2 += e; wv = fmaf(e, b[k].x - a[k].x, wv);
        e = __expf(b[k].y - m2); s2 += e; wv = fmaf(e, b[k].y - a[k].y, wv);
        e = __expf(b[k].z - m2); s2 += e; wv = fmaf(e, b[k].z - a[k].z, wv);
        e = __expf(b[k].w - m2); s2 += e; wv = fmaf(e, b[k].w - a[k].w, wv);
    }
    #pragma unroll
    for (int o = 16; o; o >>= 1) {
        s1 += __shfl_xor_sync(0xFFFFFFFFu, s1, o);
        s2 += __shfl_xor_sync(0xFFFFFFFFu, s2, o);
        wv += __shfl_xor_sync(0xFFFFFFFFu, wv, o);
    }

    if (lane == 0)
        g_row[row] = wv / s2 + (m1 + __logf(s1)) - (m2 + __logf(s2));
}

// ---- finisher (PDL): launches while engine drains; label loads pre-sync,
// g_row/g_cnt reads post-sync; g_cnt staged in smem for the gather. ----
__global__ __launch_bounds__(256) void kl_final_kernel(
    const int* __restrict__ label,
    float*     __restrict__ out)
{
    __shared__ int   scnt[C];
    __shared__ float swarp[8];
    __shared__ int   s_last;
    const int tid  = threadIdx.x;
    const int lane = tid & 31;
    const int wid  = tid >> 5;

    // ---- pre-sync: work independent of kl_main's output ----
    const int i = blockIdx.x * 256 + tid;        // int4 index, 8192 total
    int4 L = ((const int4*)label)[i];
    L.x = min(max(L.x, 0), C - 1);
    L.y = min(max(L.y, 0), C - 1);
    L.z = min(max(L.z, 0), C - 1);
    L.w = min(max(L.w, 0), C - 1);

    // wait for kl_main completion (+ memory flush)
    cudaGridDependencySynchronize();

    // ---- post-sync: stage g_cnt in smem, then gather from smem ----
    #pragma unroll
    for (int k = 0; k < 4; k++) {
        int c = tid + 256 * k;
        if (c < C) scnt[c] = g_cnt[c];
    }
    float4 v = __ldcg((const float4*)g_row + i);
    __syncthreads();

    float s = 0.f;
    s += __fdividef(v.x, (float)max(scnt[L.x], 1));
    s += __fdividef(v.y, (float)max(scnt[L.y], 1));
    s += __fdividef(v.z, (float)max(scnt[L.z], 1));
    s += __fdividef(v.w, (float)max(scnt[L.w], 1));

    #pragma unroll
    for (int o = 16; o; o >>= 1) s += __shfl_xor_sync(0xFFFFFFFFu, s, o);
    if (lane == 0) swarp[wid] = s;
    __syncthreads();
    if (tid == 0) {
        float r = 0.f;
        #pragma unroll
        for (int k = 0; k < 8; k++) r += swarp[k];
        g_part[blockIdx.x] = r;
        __threadfence();
        unsigned old = atomicAdd(&g_done, 1u);
        s_last = (old == (unsigned)(NFIN - 1)) ? 1 : 0;
    }
    __syncthreads();
    if (!s_last) return;

    // last block: deterministic fixed-order sum of the 32 partials
    if (wid == 0) {
        float r = (lane < NFIN) ? __ldcg(g_part + lane) : 0.f;
        #pragma unroll
        for (int o = 16; o; o >>= 1) r += __shfl_xor_sync(0xFFFFFFFFu, r, o);
        if (lane == 0) out[0] = r * (1.0f / (float)C);
    }
    // restore invariants for next call / graph replay
    __syncthreads();
    for (int k = tid; k < C; k += 256) g_cnt[k] = 0;
    if (tid == 0) g_done = 0u;
}

extern "C" void kernel_launch(void* const* d_in, const int* in_sizes, int n_in,
                              void* d_out, int out_size)
{
    const float* f1    = (const float*)d_in[0];
    const float* f2    = (const float*)d_in[1];
    const int*   label = (const int*)d_in[2];
    float*       out   = (float*)d_out;

    kl_main_kernel<<<NBLK, 256>>>(f1, f2, label);

    // PDL: kl_final may begin while kl_main drains; it gates its reads of
    // g_row/g_cnt with cudaGridDependencySynchronize().
    cudaLaunchConfig_t cfg = {};
    cfg.gridDim  = dim3(NFIN, 1, 1);
    cfg.blockDim = dim3(256, 1, 1);
    cudaLaunchAttribute attr[1];
    attr[0].id = cudaLaunchAttributeProgrammaticStreamSerialization;
    attr[0].val.programmaticStreamSerializationAllowed = 1;
    cfg.attrs    = attr;
    cfg.numAttrs = 1;
    cudaLaunchKernelEx(&cfg, kl_final_kernel, label, out);
}